// round 2
// baseline (speedup 1.0000x reference)
#include <cuda_runtime.h>
#include <cuda_bf16.h>

// Problem constants (fixed by reference):
//   x          : [B=32, C=2048, H=32, W=32] fp32
//   slot_assign: [B, H, W] int32 in [0, 256)
//   alpha,beta : [256, 2048] fp32
//   out = alpha[slot] * x + beta[slot]  (per-pixel channel-wise affine)

#define B_DIM   32
#define C_DIM   2048
#define HW_DIM  1024          // 32*32
#define NSLOTS  256
#define CCHUNK  64            // channels per block
#define TPB     256           // threads per block; each thread = 4 pixels

struct f8 { float v[8]; };

// 256-bit load (sm_100+): one 32B sector per request -> no gather amplification.
__device__ __forceinline__ f8 ld256(const float* p) {
    f8 r;
    asm volatile("ld.global.nc.v8.f32 {%0,%1,%2,%3,%4,%5,%6,%7}, [%8];"
        : "=f"(r.v[0]), "=f"(r.v[1]), "=f"(r.v[2]), "=f"(r.v[3]),
          "=f"(r.v[4]), "=f"(r.v[5]), "=f"(r.v[6]), "=f"(r.v[7])
        : "l"(p));
    return r;
}

__global__ __launch_bounds__(TPB)
void film_slot_kernel(const float* __restrict__ x,
                      const int*   __restrict__ slot,
                      const float* __restrict__ alpha,
                      const float* __restrict__ beta,
                      float*       __restrict__ out)
{
    const int b   = blockIdx.y;               // batch image
    const int c0  = blockIdx.x * CCHUNK;      // channel chunk base
    const int hw4 = threadIdx.x * 4;          // 4 contiguous pixels per thread

    // Per-pixel slot ids (constant across the whole channel loop).
    const int4 s4 = *reinterpret_cast<const int4*>(slot + b * HW_DIM + hw4);

    const float* __restrict__ a0 = alpha + (size_t)s4.x * C_DIM;
    const float* __restrict__ a1 = alpha + (size_t)s4.y * C_DIM;
    const float* __restrict__ a2 = alpha + (size_t)s4.z * C_DIM;
    const float* __restrict__ a3 = alpha + (size_t)s4.w * C_DIM;
    const float* __restrict__ b0 = beta  + (size_t)s4.x * C_DIM;
    const float* __restrict__ b1 = beta  + (size_t)s4.y * C_DIM;
    const float* __restrict__ b2 = beta  + (size_t)s4.z * C_DIM;
    const float* __restrict__ b3 = beta  + (size_t)s4.w * C_DIM;

    const float* __restrict__ xb = x   + (size_t)b * C_DIM * HW_DIM;
    float*       __restrict__ ob = out + (size_t)b * C_DIM * HW_DIM;

    #pragma unroll 2
    for (int cg = 0; cg < CCHUNK / 8; ++cg) {
        const int c = c0 + cg * 8;

        // 8 channels of (alpha, beta) for each of the 4 pixels' slots.
        // Each ld256 = exactly one 32B L2 sector, fully consumed.
        f8 A0 = ld256(a0 + c);
        f8 A1 = ld256(a1 + c);
        f8 A2 = ld256(a2 + c);
        f8 A3 = ld256(a3 + c);
        f8 Bt0 = ld256(b0 + c);
        f8 Bt1 = ld256(b1 + c);
        f8 Bt2 = ld256(b2 + c);
        f8 Bt3 = ld256(b3 + c);

        #pragma unroll
        for (int j = 0; j < 8; ++j) {
            const size_t off = (size_t)(c + j) * HW_DIM + hw4;
            const float4 xv = *reinterpret_cast<const float4*>(xb + off);
            float4 o;
            o.x = fmaf(A0.v[j], xv.x, Bt0.v[j]);
            o.y = fmaf(A1.v[j], xv.y, Bt1.v[j]);
            o.z = fmaf(A2.v[j], xv.z, Bt2.v[j]);
            o.w = fmaf(A3.v[j], xv.w, Bt3.v[j]);
            *reinterpret_cast<float4*>(ob + off) = o;
        }
    }
}

extern "C" void kernel_launch(void* const* d_in, const int* in_sizes, int n_in,
                              void* d_out, int out_size)
{
    const float* x     = (const float*)d_in[0];
    const int*   slot  = (const int*)  d_in[1];
    const float* alpha = (const float*)d_in[2];
    const float* beta  = (const float*)d_in[3];
    float*       out   = (float*)      d_out;

    dim3 grid(C_DIM / CCHUNK, B_DIM);   // (32, 32) = 1024 blocks
    dim3 block(TPB);                    // 256 threads, each: 4 px x 64 ch
    film_slot_kernel<<<grid, block>>>(x, slot, alpha, beta, out);
}

// round 4
// speedup vs baseline: 1.1835x; 1.1835x over previous
#include <cuda_runtime.h>
#include <cuda_bf16.h>

// out[b,c,h,w] = alpha[slot[b,h,w], c] * x[b,c,h,w] + beta[slot[b,h,w], c]
//   x, out     : [B=32, C=2048, H=32, W=32] fp32   (256 MB each)
//   slot_assign: [B, 32, 32] int32 in [0,256)
//   alpha,beta : [256, 2048] fp32                  (2 MB each, L2-resident)

#define B_DIM    32
#define C_DIM    2048
#define HW_DIM   1024          // 32*32
#define CCHUNK   64            // channels per block
#define PX_BLK   512           // pixels per block (2 per thread)
#define TPB      256

struct f8 { float v[8]; };

// 256-bit load (sm_100+): exactly one 32B L2 sector per request.
__device__ __forceinline__ f8 ld256(const float* p) {
    f8 r;
    asm volatile("ld.global.nc.v8.f32 {%0,%1,%2,%3,%4,%5,%6,%7}, [%8];"
        : "=f"(r.v[0]), "=f"(r.v[1]), "=f"(r.v[2]), "=f"(r.v[3]),
          "=f"(r.v[4]), "=f"(r.v[5]), "=f"(r.v[6]), "=f"(r.v[7])
        : "l"(p));
    return r;
}

__device__ __forceinline__ void st64_cs(float* p, float a, float b) {
    asm volatile("st.global.cs.v2.f32 [%0], {%1,%2};" :: "l"(p), "f"(a), "f"(b) : "memory");
}

__global__ __launch_bounds__(TPB, 3)
void film_slot_kernel(const float* __restrict__ x,
                      const int*   __restrict__ slot,
                      const float* __restrict__ alpha,
                      const float* __restrict__ beta,
                      float*       __restrict__ out)
{
    const int b    = blockIdx.y >> 1;                      // image
    const int half = blockIdx.y & 1;                       // which 512-pixel half
    const int c0   = blockIdx.x * CCHUNK;                  // channel chunk base
    const int hw2  = half * PX_BLK + threadIdx.x * 2;      // 2 contiguous pixels

    // Per-pixel slot ids (constant across all channels).
    const int2 s2 = *reinterpret_cast<const int2*>(slot + b * HW_DIM + hw2);

    const float* __restrict__ a0 = alpha + (size_t)s2.x * C_DIM;
    const float* __restrict__ a1 = alpha + (size_t)s2.y * C_DIM;
    const float* __restrict__ b0 = beta  + (size_t)s2.x * C_DIM;
    const float* __restrict__ b1 = beta  + (size_t)s2.y * C_DIM;

    const float* __restrict__ xb = x   + (size_t)b * (C_DIM * HW_DIM);
    float*       __restrict__ ob = out + (size_t)b * (C_DIM * HW_DIM);

    #pragma unroll 2
    for (int cg = 0; cg < CCHUNK / 8; ++cg) {
        const int c = c0 + cg * 8;

        // 8 channels of (alpha, beta) for this thread's 2 pixels: 32 regs live.
        f8 A0 = ld256(a0 + c);
        f8 A1 = ld256(a1 + c);
        f8 B0 = ld256(b0 + c);
        f8 B1 = ld256(b1 + c);

        #pragma unroll
        for (int j = 0; j < 8; ++j) {
            const size_t off = (size_t)(c + j) * HW_DIM + hw2;
            const float2 xv = *reinterpret_cast<const float2*>(xb + off);
            st64_cs(ob + off,
                    fmaf(A0.v[j], xv.x, B0.v[j]),
                    fmaf(A1.v[j], xv.y, B1.v[j]));
        }
    }
}

extern "C" void kernel_launch(void* const* d_in, const int* in_sizes, int n_in,
                              void* d_out, int out_size)
{
    const float* x     = (const float*)d_in[0];
    const int*   slot  = (const int*)  d_in[1];
    const float* alpha = (const float*)d_in[2];
    const float* beta  = (const float*)d_in[3];
    float*       out   = (float*)      d_out;

    dim3 grid(C_DIM / CCHUNK, B_DIM * 2);   // (32, 64) = 2048 blocks
    dim3 block(TPB);                        // 256 threads, each: 2 px x 64 ch
    film_slot_kernel<<<grid, block>>>(x, slot, alpha, beta, out);
}